// round 6
// baseline (speedup 1.0000x reference)
#include <cuda_runtime.h>
#include <cstdint>

// ---------------------------------------------------------------------------
// GungnirHalfKA (NNUE) batched eval, GB300 sm_103a — Round 6
// R5 + register-resident 8-deep load batches (launch_bounds(64,20) -> ~48 regs)
// ---------------------------------------------------------------------------

#define FT_IN   45056
#define FT_OUT  1024
#define NB_MAX  8

__device__ signed char g_ftq[(size_t)FT_IN * FT_OUT];   // 46 MB, int8-exact
__device__ signed char g_fc0q[NB_MAX * 16 * FT_OUT];    // 128 KB, int8-exact
__device__ unsigned    g_bq[FT_OUT / 2];                // bias, 2x i16 packed

__device__ __forceinline__ float q8f(float x) {
    return fminf(fmaxf(rintf(x), -128.f), 127.f);
}
__device__ __forceinline__ float q16f(float x) {
    return fminf(fmaxf(rintf(x), -32768.f), 32767.f);
}
__device__ __forceinline__ float q32f(float x) {
    return fminf(fmaxf(rintf(x), -2147483648.f), 2147483647.f);
}
__device__ __forceinline__ float clip127(float x) {
    return fminf(fmaxf(x, 0.f), 127.f);
}

// Sign-extend 4 int8s in v into 2x(2xint16), accumulate per-halfword.
__device__ __forceinline__ void acc4(unsigned* a, unsigned v) {
    unsigned lo, hi;
    asm("prmt.b32 %0, %1, 0, 0x9180;" : "=r"(lo) : "r"(v));
    asm("prmt.b32 %0, %1, 0, 0xB3A2;" : "=r"(hi) : "r"(v));
    a[0] = __vadd2(a[0], lo);
    a[1] = __vadd2(a[1], hi);
}
__device__ __forceinline__ void acc16(unsigned* acc, const int4& v) {
    acc4(acc + 0, (unsigned)v.x);
    acc4(acc + 2, (unsigned)v.y);
    acc4(acc + 4, (unsigned)v.z);
    acc4(acc + 6, (unsigned)v.w);
}

// ---- precompute: ft_weight -> int8, fc0_w -> int8, ft_bias -> packed i16 --
#define FT_BLOCKS  (FT_IN)
#define FC0_ELEMS  (NB_MAX * 16 * FT_OUT)
#define FC0_BLOCKS (FC0_ELEMS / 1024)

__global__ void cvt_kernel(const float* __restrict__ ftw,
                           const float* __restrict__ f0w,
                           const float* __restrict__ ftb) {
    int blk = blockIdx.x;
    if (blk < FT_BLOCKS) {
        int i = blk * 256 + threadIdx.x;
        float4 v = __ldcs(reinterpret_cast<const float4*>(ftw) + i);
        char4 c;
        c.x = (signed char)q8f(v.x);
        c.y = (signed char)q8f(v.y);
        c.z = (signed char)q8f(v.z);
        c.w = (signed char)q8f(v.w);
        reinterpret_cast<char4*>(g_ftq)[i] = c;
    } else if (blk < FT_BLOCKS + FC0_BLOCKS) {
        int i = (blk - FT_BLOCKS) * 256 + threadIdx.x;
        float4 v = __ldcs(reinterpret_cast<const float4*>(f0w) + i);
        char4 c;
        c.x = (signed char)q8f(v.x);
        c.y = (signed char)q8f(v.y);
        c.z = (signed char)q8f(v.z);
        c.w = (signed char)q8f(v.w);
        reinterpret_cast<char4*>(g_fc0q)[i] = c;
    } else {
        int t = threadIdx.x;
        #pragma unroll
        for (int h = 0; h < 2; h++) {
            int w = t * 2 + h;                 // word 0..511
            int b0 = (int)q16f(ftb[w * 2]);
            int b1 = (int)q16f(ftb[w * 2 + 1]);
            g_bq[w] = (unsigned)(b0 & 0xFFFF) | ((unsigned)b1 << 16);
        }
    }
}

// ---- main fused kernel: one 64-thread CTA per batch item ------------------
__global__ __launch_bounds__(64, 20)
void nnue_kernel(const int* __restrict__ wf,  const int* __restrict__ wo,
                 const int* __restrict__ bf,  const int* __restrict__ bo,
                 const int* __restrict__ stm, const int* __restrict__ bucket,
                 const float* __restrict__ psq,
                 const float* __restrict__ fc0b, const float* __restrict__ fc1w,
                 const float* __restrict__ fc1b, const float* __restrict__ fc2w,
                 const float* __restrict__ fc2b,
                 float* __restrict__ out, int nfeat_total, int nb)
{
    const int b    = blockIdx.x;
    const int tid  = threadIdx.x;
    const int wid  = tid >> 5;
    const int lane = tid & 31;

    __shared__ __align__(16) int      s_wf[128], s_bf[128];
    __shared__ __align__(16) unsigned s_S[FT_OUT / 4];   // clipped acc_stm u8
    __shared__ __align__(16) unsigned s_O[FT_OUT / 4];   // clipped acc_opp u8
    __shared__ __align__(16) unsigned short s_p[FT_OUT]; // pair products u16
    __shared__ float s_o0[16];
    __shared__ float s_slab[32];
    __shared__ float s_psqt, s_scalar;
    __shared__ int   s_meta[4];

    if (tid == 0) {
        int ws = wo[b];
        int we = (b + 1 < nb) ? wo[b + 1] : nfeat_total;
        int bs = bo[b];
        int be = (b + 1 < nb) ? bo[b + 1] : nfeat_total;
        s_meta[0] = ws; s_meta[1] = min(we - ws, 128);
        s_meta[2] = bs; s_meta[3] = min(be - bs, 128);
    }
    __syncthreads();
    const int ws  = s_meta[0], nw  = s_meta[1];
    const int bs  = s_meta[2], nbf = s_meta[3];

    for (int i = tid; i < nw;  i += 64) s_wf[i] = wf[ws + i];
    for (int i = tid; i < nbf; i += 64) s_bf[i] = bf[bs + i];
    __syncthreads();

    const int st = stm[b];
    const int bk = bucket[b];
    const int d0 = tid * 16;

    // ---- gather both sides; clip+pack to u8, single STS.128 per side -----
    #pragma unroll
    for (int side = 0; side < 2; side++) {
        const int* feats = side ? s_bf : s_wf;
        const int  n     = side ? nbf  : nw;
        unsigned acc[8] = {0,0,0,0,0,0,0,0};

        int f = 0;
        for (; f + 8 <= n; f += 8) {
            // Batch 8 independent LDG.128 (register-resident: ~32 data regs).
            int4 ix0 = *reinterpret_cast<const int4*>(feats + f);
            int4 ix1 = *reinterpret_cast<const int4*>(feats + f + 4);
            int4 v0 = __ldcg(reinterpret_cast<const int4*>(g_ftq + ((size_t)ix0.x << 10) + d0));
            int4 v1 = __ldcg(reinterpret_cast<const int4*>(g_ftq + ((size_t)ix0.y << 10) + d0));
            int4 v2 = __ldcg(reinterpret_cast<const int4*>(g_ftq + ((size_t)ix0.z << 10) + d0));
            int4 v3 = __ldcg(reinterpret_cast<const int4*>(g_ftq + ((size_t)ix0.w << 10) + d0));
            int4 v4 = __ldcg(reinterpret_cast<const int4*>(g_ftq + ((size_t)ix1.x << 10) + d0));
            int4 v5 = __ldcg(reinterpret_cast<const int4*>(g_ftq + ((size_t)ix1.y << 10) + d0));
            int4 v6 = __ldcg(reinterpret_cast<const int4*>(g_ftq + ((size_t)ix1.z << 10) + d0));
            int4 v7 = __ldcg(reinterpret_cast<const int4*>(g_ftq + ((size_t)ix1.w << 10) + d0));
            acc16(acc, v0); acc16(acc, v1); acc16(acc, v2); acc16(acc, v3);
            acc16(acc, v4); acc16(acc, v5); acc16(acc, v6); acc16(acc, v7);
        }
        for (; f < n; f++) {
            const int4 v = __ldcg(reinterpret_cast<const int4*>(
                g_ftq + ((size_t)feats[f] << 10) + d0));
            acc16(acc, v);
        }

        // Bias loaded HERE (not live across the loop): 2x LDG.128, L2-hot.
        const uint4 bq0 = reinterpret_cast<const uint4*>(g_bq)[tid * 2];
        const uint4 bq1 = reinterpret_cast<const uint4*>(g_bq)[tid * 2 + 1];
        const unsigned biasp[8] = {bq0.x, bq0.y, bq0.z, bq0.w,
                                   bq1.x, bq1.y, bq1.z, bq1.w};

        // +bias, clip to [0,127], pack 16 dims -> uint4, one STS.128.
        unsigned pw[4];
        #pragma unroll
        for (int j = 0; j < 4; j++) {
            unsigned a01 = __vadd2(acc[2*j],     biasp[2*j]);
            unsigned a23 = __vadd2(acc[2*j + 1], biasp[2*j + 1]);
            a01 = __vmins2(__vmaxs2(a01, 0u), 0x007F007Fu);
            a23 = __vmins2(__vmaxs2(a23, 0u), 0x007F007Fu);
            pw[j] = __byte_perm(a01, a23, 0x6420);
        }
        // white(side0) -> stm? opp : stm ; black(side1) -> stm? stm : opp
        unsigned* dst = (side ^ st) ? s_O : s_S;
        reinterpret_cast<uint4*>(dst)[tid] = make_uint4(pw[0], pw[1], pw[2], pw[3]);
    }
    __syncthreads();

    // ---- pairwise products (u16-exact), conflict-free --------------------
    #pragma unroll
    for (int h = 0; h < 2; h++) {
        int w = tid + h * 64;                  // word 0..127 (4 dims)
        unsigned a = s_S[w], c = s_S[w + 128];
        uint2 stv;
        stv.x = ((a & 0xFFu) * (c & 0xFFu)) |
                ((((a >> 8) & 0xFFu) * ((c >> 8) & 0xFFu)) << 16);
        stv.y = (((a >> 16) & 0xFFu) * ((c >> 16) & 0xFFu)) |
                (((a >> 24) * (c >> 24)) << 16);
        *reinterpret_cast<uint2*>(s_p + 4 * w) = stv;

        unsigned ao = s_O[w], co = s_O[w + 128];
        uint2 stw;
        stw.x = ((ao & 0xFFu) * (co & 0xFFu)) |
                ((((ao >> 8) & 0xFFu) * ((co >> 8) & 0xFFu)) << 16);
        stw.y = (((ao >> 16) & 0xFFu) * ((co >> 16) & 0xFFu)) |
                (((ao >> 24) * (co >> 24)) << 16);
        *reinterpret_cast<uint2*>(s_p + 512 + 4 * w) = stw;
    }
    __syncthreads();

    // ---- fc0: 16 x 1024 matvec; dp2a (s16 x s8), exact int32 -------------
    for (int o = wid; o < 16; o += 2) {
        const signed char* wrow = g_fc0q + ((bk * 16 + o) << 10);
        int isum = 0;
        #pragma unroll
        for (int c = 0; c < 4; c++) {
            int idx = (c * 32 + lane) * 8;                 // 8 dims
            uint4 pv = *reinterpret_cast<const uint4*>(s_p + idx);
            int2  wv = *reinterpret_cast<const int2*>(wrow + idx);
            isum = __dp2a_lo((int)pv.x, wv.x, isum);
            isum = __dp2a_hi((int)pv.y, wv.x, isum);
            isum = __dp2a_lo((int)pv.z, wv.y, isum);
            isum = __dp2a_hi((int)pv.w, wv.y, isum);
        }
        #pragma unroll
        for (int off = 16; off; off >>= 1)
            isum += __shfl_down_sync(0xffffffffu, isum, off);
        if (lane == 0)
            s_o0[o] = (float)isum * (1.f / 128.f) + q32f(fc0b[bk * 16 + o]);
    }
    __syncthreads();

    // ---- warp 1: psqt; warp 0: slab -> fc1 -> fc2 + skip -----------------
    if (wid == 1) {
        float ps = 0.f;
        for (int i = lane; i < nw;  i += 32)
            ps += q32f(psq[(size_t)s_wf[i] * 8 + bk]);
        for (int i = lane; i < nbf; i += 32)
            ps -= q32f(psq[(size_t)s_bf[i] * 8 + bk]);
        #pragma unroll
        for (int off = 16; off; off >>= 1)
            ps += __shfl_down_sync(0xffffffffu, ps, off);
        if (lane == 0) s_psqt = (st ? -ps : ps) * 0.5f;
    } else {
        float sl = 0.f;
        if (lane < 15) {
            float v = s_o0[lane];
            sl = clip127(v * v * (1.f / 524288.f));       // 1<<19
        } else if (lane < 30) {
            float v = s_o0[lane - 15];
            sl = clip127(v * (1.f / 64.f));
        }
        s_slab[lane] = sl;
        __syncwarp();

        const float* w1 = fc1w + (size_t)(bk * 32 + lane) * 32;
        float o1 = 0.f;
        #pragma unroll
        for (int k = 0; k < 32; k++)
            o1 += s_slab[k] * q8f(w1[k]);
        o1 += q32f(fc1b[bk * 32 + lane]);

        float a1 = clip127(o1 * (1.f / 64.f));
        float p  = a1 * q8f(fc2w[bk * 32 + lane]);
        #pragma unroll
        for (int off = 16; off; off >>= 1)
            p += __shfl_down_sync(0xffffffffu, p, off);
        if (lane == 0) {
            float scalar = p + q32f(fc2b[bk]);
            float skip   = s_o0[15] * (9600.f / 8128.f);
            s_scalar = scalar + skip;
        }
    }
    __syncthreads();

    if (tid == 0)
        out[b] = (s_psqt + s_scalar) * (1.f / 16.f);
}

extern "C" void kernel_launch(void* const* d_in, const int* in_sizes, int n_in,
                              void* d_out, int out_size)
{
    const int*   wf   = (const int*)d_in[0];
    const int*   wo   = (const int*)d_in[1];
    const int*   bfi  = (const int*)d_in[2];
    const int*   bo   = (const int*)d_in[3];
    const int*   stm  = (const int*)d_in[4];
    const int*   bkt  = (const int*)d_in[5];
    const float* ftw  = (const float*)d_in[6];
    const float* ftb  = (const float*)d_in[7];
    const float* psq  = (const float*)d_in[8];
    const float* f0w  = (const float*)d_in[9];
    const float* f0b  = (const float*)d_in[10];
    const float* f1w  = (const float*)d_in[11];
    const float* f1b  = (const float*)d_in[12];
    const float* f2w  = (const float*)d_in[13];
    const float* f2b  = (const float*)d_in[14];
    float* out = (float*)d_out;

    const int nb = in_sizes[4];
    const int nfeat_total = in_sizes[0];

    cvt_kernel<<<FT_BLOCKS + FC0_BLOCKS + 1, 256>>>(ftw, f0w, ftb);

    nnue_kernel<<<nb, 64>>>(wf, wo, bfi, bo, stm, bkt,
                            psq, f0b, f1w, f1b, f2w, f2b,
                            out, nfeat_total, nb);
}